// round 1
// baseline (speedup 1.0000x reference)
#include <cuda_runtime.h>

// Problem constants
#define B_SZ   4
#define C_LEN  2048
#define H_N    8
#define DK_    64
#define DV_    128
#define DIN_   1024

#define QK_COLS (H_N * DK_)   // 512
#define V_COLS  (H_N * DV_)   // 1024
#define M_ROWS  (B_SZ * C_LEN) // 8192

// Scratch (device globals: allocation-free per harness rules)
__device__ __align__(16) float g_q[B_SZ * C_LEN * QK_COLS];             // 16 MB
__device__ __align__(16) float g_k[B_SZ * C_LEN * QK_COLS];             // 16 MB
__device__ __align__(16) float g_v[B_SZ * C_LEN * V_COLS];              // 32 MB
__device__ __align__(16) float g_s[(size_t)B_SZ * H_N * C_LEN * C_LEN]; // 512 MB
__device__ __align__(16) float g_ao[B_SZ * C_LEN * V_COLS];             // 32 MB

// ---------------------------------------------------------------------------
// Generic NT SGEMM:  C[M,N] = A[M,K] @ W[N,K]^T + bias[N]
// 128x128 tile, BK=8, 256 threads, 8x8 register tile per thread.
// ---------------------------------------------------------------------------
__global__ void __launch_bounds__(256) gemm_nt_bias(
    const float* __restrict__ A, const float* __restrict__ W,
    const float* __restrict__ bias, float* __restrict__ C,
    int M, int N, int K)
{
    __shared__ float As[8][132];
    __shared__ float Bs[8][132];

    const int tid = threadIdx.x;
    const int bm = blockIdx.y * 128;
    const int bn = blockIdx.x * 128;

    const int lrow = tid >> 1;          // 0..127
    const int lcol = (tid & 1) * 4;     // 0 or 4
    const int tx = tid & 15;
    const int ty = tid >> 4;

    const float* Aptr = A + (size_t)(bm + lrow) * K + lcol;
    const float* Wptr = W + (size_t)(bn + lrow) * K + lcol;

    float acc[8][8];
    #pragma unroll
    for (int i = 0; i < 8; i++)
        #pragma unroll
        for (int j = 0; j < 8; j++) acc[i][j] = 0.f;

    for (int k0 = 0; k0 < K; k0 += 8) {
        float4 av = *(const float4*)(Aptr + k0);
        float4 wv = *(const float4*)(Wptr + k0);
        As[lcol + 0][lrow] = av.x; As[lcol + 1][lrow] = av.y;
        As[lcol + 2][lrow] = av.z; As[lcol + 3][lrow] = av.w;
        Bs[lcol + 0][lrow] = wv.x; Bs[lcol + 1][lrow] = wv.y;
        Bs[lcol + 2][lrow] = wv.z; Bs[lcol + 3][lrow] = wv.w;
        __syncthreads();
        #pragma unroll
        for (int kk = 0; kk < 8; kk++) {
            float a[8], b[8];
            *(float4*)(a)     = *(const float4*)&As[kk][ty * 8];
            *(float4*)(a + 4) = *(const float4*)&As[kk][ty * 8 + 4];
            *(float4*)(b)     = *(const float4*)&Bs[kk][tx * 8];
            *(float4*)(b + 4) = *(const float4*)&Bs[kk][tx * 8 + 4];
            #pragma unroll
            for (int i = 0; i < 8; i++)
                #pragma unroll
                for (int j = 0; j < 8; j++)
                    acc[i][j] += a[i] * b[j];
        }
        __syncthreads();
    }

    #pragma unroll
    for (int i = 0; i < 8; i++) {
        const int row = bm + ty * 8 + i;
        #pragma unroll
        for (int j = 0; j < 8; j += 4) {
            const int col = bn + tx * 8 + j;
            float4 o;
            o.x = acc[i][j]     + bias[col];
            o.y = acc[i][j + 1] + bias[col + 1];
            o.z = acc[i][j + 2] + bias[col + 2];
            o.w = acc[i][j + 3] + bias[col + 3];
            *(float4*)(C + (size_t)row * N + col) = o;
        }
    }
}

// ---------------------------------------------------------------------------
// Batched scores: S_z[q,k] = (Q_z[q,:] . K_z[k,:] + mask[b,q]) / 8
// z = b*H + h; Q_z/K_z are contiguous [2048,64] slices; S_z is [2048,2048].
// grid (16, 16, 32)
// ---------------------------------------------------------------------------
__global__ void __launch_bounds__(256) gemm_scores(
    const float* __restrict__ Q, const float* __restrict__ Kk,
    const float* __restrict__ mask)
{
    __shared__ float As[8][132];
    __shared__ float Bs[8][132];

    const int z = blockIdx.z;
    const float* A = Q  + (size_t)z * (C_LEN * DK_);
    const float* W = Kk + (size_t)z * (C_LEN * DK_);
    float* Cc = g_s + (size_t)z * ((size_t)C_LEN * C_LEN);
    const float* mrow = mask + (z >> 3) * C_LEN;

    const int tid = threadIdx.x;
    const int bm = blockIdx.y * 128;
    const int bn = blockIdx.x * 128;
    const int lrow = tid >> 1;
    const int lcol = (tid & 1) * 4;
    const int tx = tid & 15;
    const int ty = tid >> 4;

    const float* Aptr = A + (size_t)(bm + lrow) * DK_ + lcol;
    const float* Wptr = W + (size_t)(bn + lrow) * DK_ + lcol;

    float acc[8][8];
    #pragma unroll
    for (int i = 0; i < 8; i++)
        #pragma unroll
        for (int j = 0; j < 8; j++) acc[i][j] = 0.f;

    #pragma unroll
    for (int k0 = 0; k0 < DK_; k0 += 8) {
        float4 av = *(const float4*)(Aptr + k0);
        float4 wv = *(const float4*)(Wptr + k0);
        As[lcol + 0][lrow] = av.x; As[lcol + 1][lrow] = av.y;
        As[lcol + 2][lrow] = av.z; As[lcol + 3][lrow] = av.w;
        Bs[lcol + 0][lrow] = wv.x; Bs[lcol + 1][lrow] = wv.y;
        Bs[lcol + 2][lrow] = wv.z; Bs[lcol + 3][lrow] = wv.w;
        __syncthreads();
        #pragma unroll
        for (int kk = 0; kk < 8; kk++) {
            float a[8], b[8];
            *(float4*)(a)     = *(const float4*)&As[kk][ty * 8];
            *(float4*)(a + 4) = *(const float4*)&As[kk][ty * 8 + 4];
            *(float4*)(b)     = *(const float4*)&Bs[kk][tx * 8];
            *(float4*)(b + 4) = *(const float4*)&Bs[kk][tx * 8 + 4];
            #pragma unroll
            for (int i = 0; i < 8; i++)
                #pragma unroll
                for (int j = 0; j < 8; j++)
                    acc[i][j] += a[i] * b[j];
        }
        __syncthreads();
    }

    #pragma unroll
    for (int i = 0; i < 8; i++) {
        const int row = bm + ty * 8 + i;
        const float mv = mrow[row];
        #pragma unroll
        for (int j = 0; j < 8; j += 4) {
            const int col = bn + tx * 8 + j;
            float4 o;
            o.x = (acc[i][j]     + mv) * 0.125f;
            o.y = (acc[i][j + 1] + mv) * 0.125f;
            o.z = (acc[i][j + 2] + mv) * 0.125f;
            o.w = (acc[i][j + 3] + mv) * 0.125f;
            *(float4*)(Cc + (size_t)row * C_LEN + col) = o;
        }
    }
}

// ---------------------------------------------------------------------------
// Column softmax (over the QUERY axis, per reference): for each (z, col):
//   P[q,col] = exp(S[q,col]-m) / sum_q exp(S[q,col]-m)
// grid (8, 32), 256 threads; one thread per column, coalesced across threads.
// ---------------------------------------------------------------------------
__global__ void __launch_bounds__(256) softmax_col()
{
    const int z = blockIdx.y;
    const int col = blockIdx.x * 256 + threadIdx.x;
    float* base = g_s + (size_t)z * ((size_t)C_LEN * C_LEN) + col;

    float m = -1e30f;
    #pragma unroll 8
    for (int q = 0; q < C_LEN; q++)
        m = fmaxf(m, base[(size_t)q * C_LEN]);

    float sum = 0.f;
    #pragma unroll 8
    for (int q = 0; q < C_LEN; q++)
        sum += __expf(base[(size_t)q * C_LEN] - m);

    const float inv = 1.0f / sum;
    #pragma unroll 8
    for (int q = 0; q < C_LEN; q++) {
        float vv = __expf(base[(size_t)q * C_LEN] - m) * inv;
        base[(size_t)q * C_LEN] = vv;
    }
}

// ---------------------------------------------------------------------------
// Batched NN GEMM: AO_z[q,d] = P_z[q,:] @ V_z[:,d]
// P_z: [2048,2048] row-major; V_z: [2048,128] row-major; AO_z: [2048,128].
// grid (16, 32): x = M-tile, y = z. Full N (128) in one block column.
// ---------------------------------------------------------------------------
__global__ void __launch_bounds__(256) gemm_av()
{
    __shared__ float As[8][132];
    __shared__ float Bs[8][132];

    const int z = blockIdx.y;
    const float* A = g_s + (size_t)z * ((size_t)C_LEN * C_LEN);
    const float* V = g_v + (size_t)z * (C_LEN * DV_);
    float* Cc = g_ao + (size_t)z * (C_LEN * DV_);

    const int tid = threadIdx.x;
    const int bm = blockIdx.x * 128;
    const int lrow = tid >> 1;
    const int lcol = (tid & 1) * 4;
    const int brow = tid >> 5;          // 0..7
    const int bcol = (tid & 31) * 4;    // 0..124
    const int tx = tid & 15;
    const int ty = tid >> 4;

    const float* Aptr = A + (size_t)(bm + lrow) * C_LEN + lcol;

    float acc[8][8];
    #pragma unroll
    for (int i = 0; i < 8; i++)
        #pragma unroll
        for (int j = 0; j < 8; j++) acc[i][j] = 0.f;

    for (int k0 = 0; k0 < C_LEN; k0 += 8) {
        float4 av = *(const float4*)(Aptr + k0);
        float4 vv = *(const float4*)(V + (size_t)(k0 + brow) * DV_ + bcol);
        As[lcol + 0][lrow] = av.x; As[lcol + 1][lrow] = av.y;
        As[lcol + 2][lrow] = av.z; As[lcol + 3][lrow] = av.w;
        *(float4*)&Bs[brow][bcol] = vv;
        __syncthreads();
        #pragma unroll
        for (int kk = 0; kk < 8; kk++) {
            float a[8], b[8];
            *(float4*)(a)     = *(const float4*)&As[kk][ty * 8];
            *(float4*)(a + 4) = *(const float4*)&As[kk][ty * 8 + 4];
            *(float4*)(b)     = *(const float4*)&Bs[kk][tx * 8];
            *(float4*)(b + 4) = *(const float4*)&Bs[kk][tx * 8 + 4];
            #pragma unroll
            for (int i = 0; i < 8; i++)
                #pragma unroll
                for (int j = 0; j < 8; j++)
                    acc[i][j] += a[i] * b[j];
        }
        __syncthreads();
    }

    #pragma unroll
    for (int i = 0; i < 8; i++) {
        const int row = bm + ty * 8 + i;
        #pragma unroll
        for (int j = 0; j < 8; j += 4) {
            const int col = tx * 8 + j;
            float4 o;
            o.x = acc[i][j];
            o.y = acc[i][j + 1];
            o.z = acc[i][j + 2];
            o.w = acc[i][j + 3];
            *(float4*)(Cc + (size_t)row * DV_ + col) = o;
        }
    }
}

// ---------------------------------------------------------------------------
extern "C" void kernel_launch(void* const* d_in, const int* in_sizes, int n_in,
                              void* d_out, int out_size)
{
    const float* x    = (const float*)d_in[0];
    const float* mask = (const float*)d_in[1];
    const float* Mq_w = (const float*)d_in[2];
    const float* Mq_b = (const float*)d_in[3];
    const float* Mk_w = (const float*)d_in[4];
    const float* Mk_b = (const float*)d_in[5];
    const float* Mv_w = (const float*)d_in[6];
    const float* Mv_b = (const float*)d_in[7];
    const float* Wo_w = (const float*)d_in[8];
    const float* Wo_b = (const float*)d_in[9];
    float* out = (float*)d_out;

    float *q, *k, *v, *ao;
    cudaGetSymbolAddress((void**)&q,  g_q);
    cudaGetSymbolAddress((void**)&k,  g_k);
    cudaGetSymbolAddress((void**)&v,  g_v);
    cudaGetSymbolAddress((void**)&ao, g_ao);

    dim3 blk(256);

    // QKV projections: [8192,1024] @ [Nout,1024]^T + b
    gemm_nt_bias<<<dim3(QK_COLS / 128, M_ROWS / 128), blk>>>(x, Mq_w, Mq_b, q, M_ROWS, QK_COLS, DIN_);
    gemm_nt_bias<<<dim3(QK_COLS / 128, M_ROWS / 128), blk>>>(x, Mk_w, Mk_b, k, M_ROWS, QK_COLS, DIN_);
    gemm_nt_bias<<<dim3(V_COLS / 128,  M_ROWS / 128), blk>>>(x, Mv_w, Mv_b, v, M_ROWS, V_COLS, DIN_);

    // S = (Q K^T + mask) / sqrt(dk), batched over z = b*H + h
    gemm_scores<<<dim3(C_LEN / 128, C_LEN / 128, B_SZ * H_N), blk>>>(q, k, mask);

    // Softmax over query axis (columns of S)
    softmax_col<<<dim3(C_LEN / 256, B_SZ * H_N), blk>>>();

    // AO = P @ V, batched
    gemm_av<<<dim3(C_LEN / 128, B_SZ * H_N), blk>>>();

    // Output projection: [8192,1024] @ [1024,1024]^T + b -> d_out
    gemm_nt_bias<<<dim3(V_COLS / 128, M_ROWS / 128), blk>>>(ao, Wo_w, Wo_b, out, M_ROWS, V_COLS, DIN_);
}